// round 16
// baseline (speedup 1.0000x reference)
#include <cuda_runtime.h>
#include <cstdint>

// Problem constants:
//   features: [B=4, C=256, H=64, W=64] fp32
//   rois:     [R=2048, 5] (batch, x1, y1, x2, y2), SPATIAL_SCALE = 0.25
//   Grid positions h=w={0,7,...,63} are EXACT integers -> bilinear == gather.
//   output:   [R, C, 9, 9] fp32  (maxpool 2x2 s1 of region-of-discard-masked 10x10)

#define BATCH 4
#define NCH   256
#define NPOS  100        // 10x10 grid per channel
#define CHB   64         // channels per block
#define NCHUNK (NCH / CHB)          // 4
#define THREADS 256      // 64 channels x 4 column-strips
#define NROI  2048

// Transposed gather: G_t[b][pos][c] = features[b,c,7i,7j], channels contiguous.
__device__ float g_Gt[BATCH * NPOS * NCH];
// Batch-grouped ROI permutation (any permutation is correct; grouping lets
// adjacent pairs share G loads).
__device__ int g_perm[NROI];

__global__ void gather_grid_kernel(const float* __restrict__ feat) {
    int idx = blockIdx.x * blockDim.x + threadIdx.x;   // b*100*256 + p*256 + c
    if (idx >= BATCH * NPOS * NCH) return;
    int c  = idx % NCH;
    int bp = idx / NCH;
    int p  = bp % NPOS;
    int b  = bp / NPOS;
    int i = p / 10;
    int j = p % 10;
    g_Gt[idx] = feat[(((b * NCH + c) * 64) + i * 7) * 64 + j * 7];
}

// Deterministic counting sort of ROI indices by batch (stable). One block,
// 256 threads x 8 ROIs each.
__global__ __launch_bounds__(256) void perm_kernel(const float* __restrict__ rois) {
    __shared__ int warpbase[4][8];   // exclusive prefix of warp totals per batch
    __shared__ int batchbase[4];
    const int t = threadIdx.x;
    const int lane = t & 31, warp = t >> 5;

    int b[8];
    int lc[4] = {0, 0, 0, 0};
    #pragma unroll
    for (int k = 0; k < 8; k++) {
        b[k] = (int)rois[(t * 8 + k) * 5];
        lc[b[k]]++;
    }
    int pre[4];
    #pragma unroll
    for (int q = 0; q < 4; q++) {
        int s = lc[q];
        #pragma unroll
        for (int d = 1; d < 32; d <<= 1) {
            int u = __shfl_up_sync(0xffffffffu, s, d);
            if (lane >= d) s += u;
        }
        pre[q] = s - lc[q];                 // exclusive within warp
        if (lane == 31) warpbase[q][warp] = s;   // warp total (temporarily)
    }
    __syncthreads();
    if (t == 0) {
        int tot[4];
        for (int q = 0; q < 4; q++) {
            tot[q] = 0;
            for (int w = 0; w < 8; w++) {
                int x = warpbase[q][w];
                warpbase[q][w] = tot[q];
                tot[q] += x;
            }
        }
        int acc = 0;
        for (int q = 0; q < 4; q++) { batchbase[q] = acc; acc += tot[q]; }
    }
    __syncthreads();
    int off[4];
    #pragma unroll
    for (int q = 0; q < 4; q++)
        off[q] = batchbase[q] + warpbase[q][warp] + pre[q];
    #pragma unroll
    for (int k = 0; k < 8; k++)
        g_perm[off[b[k]]++] = t * 8 + k;
}

// Front-batched unconditional loads of rows r0..r0+4 (compile-time offsets,
// MLP = 5*NCOLS).
template<int NCOLS>
__device__ __forceinline__ void loadv(float v[5][NCOLS],
                                      const float* __restrict__ gt, int r0)
{
    #pragma unroll
    for (int i = 0; i < 5; i++)
        #pragma unroll
        for (int k = 0; k < NCOLS; k++)
            v[i][k] = __ldg(&gt[((r0 + i) * 10 + k) * NCH]);
}

// Mask (FMA pipe, non-destructive) + horizontal/vertical max for 5 grid rows
// starting at grid row R0. mw[k] in {-1,0}, mh in {1,0}:
//   m = fmaf(v, mh*mw, v) -> inside: v - v = +0 exactly; outside: unchanged.
// R0==0 primes hp from row 0 and emits output rows 0..3; R0==5 emits 4..8.
template<int NCOLS, int R0>
__device__ __forceinline__ void emit(const float v[5][NCOLS],
                                     float* __restrict__ so,
                                     const float* mw, float y1, float y2,
                                     float hp[NCOLS - 1])
{
    #pragma unroll
    for (int i = 0; i < 5; i++) {
        const int gi = R0 + i;
        float h = (float)gi * 7.0f;
        float mh = ((h >= y1) && (h <= y2)) ? 1.0f : 0.0f;
        float m[NCOLS];
        #pragma unroll
        for (int k = 0; k < NCOLS; k++)
            m[k] = fmaf(v[i][k], mh * mw[k], v[i][k]);
        float hc[NCOLS - 1];
        #pragma unroll
        for (int k = 0; k < NCOLS - 1; k++)
            hc[k] = fmaxf(m[k], m[k + 1]);
        if (gi > 0) {
            #pragma unroll
            for (int k = 0; k < NCOLS - 1; k++)
                so[(gi - 1) * 9 + k] = fmaxf(hp[k], hc[k]);
        }
        #pragma unroll
        for (int k = 0; k < NCOLS - 1; k++)
            hp[k] = hc[k];
    }
}

// Process one column-strip for a PAIR of ROIs sharing the loaded G window.
template<int NCOLS>
__device__ __forceinline__ void work(const float* __restrict__ g0,
                                     const float* __restrict__ g1,
                                     float* __restrict__ so0,
                                     float* __restrict__ so1,
                                     float x1a, float x2a, float y1a, float y2a,
                                     float x1b, float x2b, float y1b, float y2b,
                                     int c0, bool diff)
{
    float mw0[NCOLS], mw1[NCOLS];
    #pragma unroll
    for (int k = 0; k < NCOLS; k++) {
        float w = (float)(c0 + k) * 7.0f;
        mw0[k] = ((w >= x1a) && (w <= x2a)) ? -1.0f : 0.0f;
        mw1[k] = ((w >= x1b) && (w <= x2b)) ? -1.0f : 0.0f;
    }
    float hp0[NCOLS - 1], hp1[NCOLS - 1];
    float v[5][NCOLS];

    // Phase A: grid rows 0..4 -> output rows 0..3 for both ROIs.
    loadv<NCOLS>(v, g0, 0);
    emit<NCOLS, 0>(v, so0, mw0, y1a, y2a, hp0);
    if (diff) loadv<NCOLS>(v, g1, 0);
    emit<NCOLS, 0>(v, so1, mw1, y1b, y2b, hp1);

    // Phase B: grid rows 5..9 -> output rows 4..8 (hp carries row 4).
    loadv<NCOLS>(v, g0, 5);
    emit<NCOLS, 5>(v, so0, mw0, y1a, y2a, hp0);
    if (diff) loadv<NCOLS>(v, g1, 5);
    emit<NCOLS, 5>(v, so1, mw1, y1b, y2b, hp1);
}

__global__ __launch_bounds__(THREADS, 4) void rod_align_max_kernel(
    const float* __restrict__ rois,
    float* __restrict__ out)
{
    __shared__ __align__(16) float sout[2][CHB * 81];   // 2 x 20736 B

    const int pair  = blockIdx.x;
    const int chunk = blockIdx.y;
    const int tid   = threadIdx.x;
    // 4 column-strips; within each strip, warps hold 32 consecutive channels.
    //   q=0: cols 0..3 -> j=0..2     q=1: cols 3..5 -> j=3..4
    //   q=2: cols 5..7 -> j=5..6     q=3: cols 7..9 -> j=7..8
    const int c = tid & (CHB - 1);
    const int q = tid >> 6;

    const int r0 = g_perm[pair * 2];
    const int r1 = g_perm[pair * 2 + 1];

    const float x1a = rois[r0 * 5 + 1] * 0.25f;
    const float y1a = rois[r0 * 5 + 2] * 0.25f;
    const float x2a = rois[r0 * 5 + 3] * 0.25f;
    const float y2a = rois[r0 * 5 + 4] * 0.25f;
    const int   b0  = (int)rois[r0 * 5 + 0];
    const float x1b = rois[r1 * 5 + 1] * 0.25f;
    const float y1b = rois[r1 * 5 + 2] * 0.25f;
    const float x2b = rois[r1 * 5 + 3] * 0.25f;
    const float y2b = rois[r1 * 5 + 4] * 0.25f;
    const int   b1  = (int)rois[r1 * 5 + 0];
    const bool diff = (b1 != b0);

    const float* g0 = g_Gt + b0 * (NPOS * NCH) + chunk * CHB + c;
    const float* g1 = g_Gt + b1 * (NPOS * NCH) + chunk * CHB + c;
    float* so0 = sout[0] + c * 81;     // stride 81 (odd) -> conflict-free STS
    float* so1 = sout[1] + c * 81;

    if (q == 0)
        work<4>(g0,           g1,           so0,     so1,
                x1a, x2a, y1a, y2a, x1b, x2b, y1b, y2b, 0, diff);
    else if (q == 1)
        work<3>(g0 + 3 * NCH, g1 + 3 * NCH, so0 + 3, so1 + 3,
                x1a, x2a, y1a, y2a, x1b, x2b, y1b, y2b, 3, diff);
    else if (q == 2)
        work<3>(g0 + 5 * NCH, g1 + 5 * NCH, so0 + 5, so1 + 5,
                x1a, x2a, y1a, y2a, x1b, x2b, y1b, y2b, 5, diff);
    else
        work<3>(g0 + 7 * NCH, g1 + 7 * NCH, so0 + 7, so1 + 7,
                x1a, x2a, y1a, y2a, x1b, x2b, y1b, y2b, 7, diff);

    // Hand both 20736B staged blocks to TMA for the global writes.
    asm volatile("fence.proxy.async.shared::cta;" ::: "memory");
    __syncthreads();
    if (tid == 0) {
        uint32_t saddr0, saddr1;
        asm("{ .reg .u64 t; cvta.to.shared.u64 t, %1; cvt.u32.u64 %0, t; }"
            : "=r"(saddr0) : "l"(&sout[0][0]));
        asm("{ .reg .u64 t; cvta.to.shared.u64 t, %1; cvt.u32.u64 %0, t; }"
            : "=r"(saddr1) : "l"(&sout[1][0]));
        float* d0 = out + (size_t)(r0 * NCH + chunk * CHB) * 81;
        float* d1 = out + (size_t)(r1 * NCH + chunk * CHB) * 81;
        asm volatile(
            "cp.async.bulk.global.shared::cta.bulk_group [%0], [%1], %2;"
            :: "l"(d0), "r"(saddr0), "r"((int)(CHB * 81 * 4)) : "memory");
        asm volatile(
            "cp.async.bulk.global.shared::cta.bulk_group [%0], [%1], %2;"
            :: "l"(d1), "r"(saddr1), "r"((int)(CHB * 81 * 4)) : "memory");
        asm volatile("cp.async.bulk.commit_group;" ::: "memory");
        // Must not exit the CTA while TMA is still reading our smem.
        asm volatile("cp.async.bulk.wait_group.read 0;" ::: "memory");
    }
}

extern "C" void kernel_launch(void* const* d_in, const int* in_sizes, int n_in,
                              void* d_out, int out_size) {
    const float* features = (const float*)d_in[0];   // [4,256,64,64]
    const float* rois     = (const float*)d_in[1];   // [2048,5]
    float* out = (float*)d_out;                      // [2048,256,9,9]

    int n_g = BATCH * NPOS * NCH;
    gather_grid_kernel<<<(n_g + 255) / 256, 256>>>(features);
    perm_kernel<<<1, 256>>>(rois);

    dim3 grid(NROI / 2, NCHUNK);                     // (1024, 4)
    rod_align_max_kernel<<<grid, THREADS>>>(rois, out);
}

// round 17
// speedup vs baseline: 1.2381x; 1.2381x over previous
#include <cuda_runtime.h>
#include <cstdint>

// Problem constants:
//   features: [B=4, C=256, H=64, W=64] fp32
//   rois:     [R=2048, 5] (batch, x1, y1, x2, y2), SPATIAL_SCALE = 0.25
//   Grid positions h=w={0,7,...,63} are EXACT integers -> bilinear == gather.
//   output:   [R, C, 9, 9] fp32  (maxpool 2x2 s1 of region-of-discard-masked 10x10)

#define BATCH 4
#define NCH   256
#define NPOS  100        // 10x10 grid per channel
#define CHB   64         // channels per block
#define NCHUNK (NCH / CHB)
#define THREADS 128      // 64 channels x 2 column-strips (6 cols / 5 cols)

// Transposed gather: G_t[b][pos][c] = features[b,c,7i,7j], channels contiguous.
__device__ float g_Gt[BATCH * NPOS * NCH];

// Coalesced gather: one warp per (b,c,i) feature row. Lanes 0-15 read the
// whole 256B row via float4 (2 coalesced LDG.128), shuffles extract the 10
// samples at x=7j, lanes 0-9 store into the transposed layout.
__global__ __launch_bounds__(256) void gather_grid_kernel(const float* __restrict__ feat) {
    const int gwarp = (blockIdx.x * 256 + threadIdx.x) >> 5;  // row id
    const int lane  = threadIdx.x & 31;
    if (gwarp >= BATCH * NCH * 10) return;

    const int i  = gwarp % 10;        // grid row
    const int bc = gwarp / 10;        // b*256 + c
    const int c  = bc % NCH;
    const int b  = bc / NCH;

    const float4* row = (const float4*)(feat + ((size_t)bc * 64 + i * 7) * 64);
    float4 v = make_float4(0.f, 0.f, 0.f, 0.f);
    if (lane < 16) v = __ldg(row + lane);

    // sample j sits at float index 7j: source lane (7j)>>2, component (7j)&3
    const int j    = lane;
    const int src  = (7 * j) >> 2;
    const int comp = (7 * j) & 3;
    float x = __shfl_sync(0xffffffffu, v.x, src);
    float y = __shfl_sync(0xffffffffu, v.y, src);
    float z = __shfl_sync(0xffffffffu, v.z, src);
    float w = __shfl_sync(0xffffffffu, v.w, src);
    float val = (comp == 0) ? x : (comp == 1) ? y : (comp == 2) ? z : w;

    if (j < 10)
        g_Gt[(b * NPOS + i * 10 + j) * NCH + c] = val;
}

// Load + mask NROWS x NCOLS window starting at grid row r0 (front-batched
// unconditional LDGs, compile-time offsets; masking on the FMA pipe:
// mw[k] in {-1,0}, mh in {1,0}; v = fmaf(v, mh*mw, v)
//   -> inside: v - v = +0 exactly; outside: v unchanged).
template<int NROWS, int NCOLS>
__device__ __forceinline__ void load_rows(float v[NROWS][NCOLS],
                                          const float* __restrict__ gt,
                                          int r0, const float* mw,
                                          float y1, float y2)
{
    #pragma unroll
    for (int i = 0; i < NROWS; i++)
        #pragma unroll
        for (int k = 0; k < NCOLS; k++)
            v[i][k] = __ldg(&gt[((r0 + i) * 10 + k) * NCH]);

    #pragma unroll
    for (int i = 0; i < NROWS; i++) {
        float h = (float)(r0 + i) * 7.0f;
        float mh = ((h >= y1) && (h <= y2)) ? 1.0f : 0.0f;
        #pragma unroll
        for (int k = 0; k < NCOLS; k++)
            v[i][k] = fmaf(v[i][k], mh * mw[k], v[i][k]);
    }
}

// One column-strip of NCOLS grid columns -> NCOLS-1 output columns.
// Two 5-row phases (MLP = 5*NCOLS each), live window 5*NCOLS floats.
template<int NCOLS>
__device__ __forceinline__ void strip(const float* __restrict__ gt,
                                      float* __restrict__ so,
                                      float x1, float x2, float y1, float y2,
                                      int c0)
{
    float mw[NCOLS];
    #pragma unroll
    for (int k = 0; k < NCOLS; k++) {
        float w = (float)(c0 + k) * 7.0f;
        mw[k] = ((w >= x1) && (w <= x2)) ? -1.0f : 0.0f;
    }

    float v[5][NCOLS];
    float hp[NCOLS - 1];

    // ---- Phase A: rows 0..4 -> output rows 0..3 ----
    load_rows<5, NCOLS>(v, gt, 0, mw, y1, y2);

    #pragma unroll
    for (int k = 0; k < NCOLS - 1; k++)
        hp[k] = fmaxf(v[0][k], v[0][k + 1]);
    #pragma unroll
    for (int i = 1; i < 5; i++) {
        float hc[NCOLS - 1];
        #pragma unroll
        for (int k = 0; k < NCOLS - 1; k++)
            hc[k] = fmaxf(v[i][k], v[i][k + 1]);
        #pragma unroll
        for (int k = 0; k < NCOLS - 1; k++)
            so[(i - 1) * 9 + k] = fmaxf(hp[k], hc[k]);
        #pragma unroll
        for (int k = 0; k < NCOLS - 1; k++)
            hp[k] = hc[k];
    }

    // ---- Phase B: rows 5..9 -> output rows 4..8 (hp carries row 4) ----
    load_rows<5, NCOLS>(v, gt, 5, mw, y1, y2);

    #pragma unroll
    for (int i = 0; i < 5; i++) {
        float hc[NCOLS - 1];
        #pragma unroll
        for (int k = 0; k < NCOLS - 1; k++)
            hc[k] = fmaxf(v[i][k], v[i][k + 1]);
        #pragma unroll
        for (int k = 0; k < NCOLS - 1; k++)
            so[(i + 4) * 9 + k] = fmaxf(hp[k], hc[k]);
        #pragma unroll
        for (int k = 0; k < NCOLS - 1; k++)
            hp[k] = hc[k];
    }
}

__global__ __launch_bounds__(THREADS, 8) void rod_align_max_kernel(
    const float* __restrict__ rois,
    float* __restrict__ out)
{
    __shared__ __align__(16) float sout[CHB * 81];   // 20736 B staged outputs

    const int r     = blockIdx.x;      // roi
    const int chunk = blockIdx.y;      // channel chunk
    const int tid   = threadIdx.x;
    // 2 column-strips; within each strip, warps hold 32 consecutive channels.
    //   q=0 (warps 0-1): cols 0..5 -> j=0..4
    //   q=1 (warps 2-3): cols 5..9 -> j=5..8
    const int c = tid & (CHB - 1);     // channel within chunk
    const int q = tid >> 6;            // strip id

    const float x1 = rois[r * 5 + 1] * 0.25f;
    const float y1 = rois[r * 5 + 2] * 0.25f;
    const float x2 = rois[r * 5 + 3] * 0.25f;
    const float y2 = rois[r * 5 + 4] * 0.25f;
    const int   b  = (int)rois[r * 5 + 0];

    const float* gbase = g_Gt + b * (NPOS * NCH) + chunk * CHB + c;
    float* so = sout + c * 81;         // stride 81 (odd) -> conflict-free STS

    if (q == 0) strip<6>(gbase,           so,     x1, x2, y1, y2, 0);
    else        strip<5>(gbase + 5 * NCH, so + 5, x1, x2, y1, y2, 5);

    // Hand the 20736B contiguous staged block to TMA for the global write.
    asm volatile("fence.proxy.async.shared::cta;" ::: "memory");
    __syncthreads();
    if (tid == 0) {
        uint32_t saddr;
        asm("{ .reg .u64 t; cvta.to.shared.u64 t, %1; cvt.u32.u64 %0, t; }"
            : "=r"(saddr) : "l"(sout));
        float* gdst = out + (size_t)(r * NCH + chunk * CHB) * 81;
        asm volatile(
            "cp.async.bulk.global.shared::cta.bulk_group [%0], [%1], %2;"
            :: "l"(gdst), "r"(saddr), "r"((int)(CHB * 81 * 4)) : "memory");
        asm volatile("cp.async.bulk.commit_group;" ::: "memory");
        // Must not exit the CTA while TMA is still reading our smem.
        asm volatile("cp.async.bulk.wait_group.read 0;" ::: "memory");
    }
}

extern "C" void kernel_launch(void* const* d_in, const int* in_sizes, int n_in,
                              void* d_out, int out_size) {
    const float* features = (const float*)d_in[0];   // [4,256,64,64]
    const float* rois     = (const float*)d_in[1];   // [2048,5]
    float* out = (float*)d_out;                      // [2048,256,9,9]

    const int R = in_sizes[1] / 5;                   // 2048

    // One warp per (b,c,i) row: 10240 warps = 1280 blocks of 256.
    int n_warps = BATCH * NCH * 10;
    gather_grid_kernel<<<(n_warps * 32 + 255) / 256, 256>>>(features);

    dim3 grid(R, NCHUNK);
    rod_align_max_kernel<<<grid, THREADS>>>(rois, out);
}